// round 15
// baseline (speedup 1.0000x reference)
#include <cuda_runtime.h>
#include <cstdint>
#include <math.h>

#define BB   64
#define NN   64
#define DD   256
#define LAPD 16
#define MM   2016          // N*(N-1)/2
#define SEQ  2081          // 1 + N + M

__device__ float g_proju[BB * NN * DD];   // 4 MB (C folded in)
__device__ float g_projv[BB * NN * DD];   // 4 MB
__device__ unsigned short g_edge[BB * MM];
__device__ int g_count[BB];

// Map linear upper-tri index m -> (i, j), i<j, row-major (triu_indices order)
__device__ __forceinline__ void m2ij(int m, int& i, int& j) {
    int ii = (int)((127.0 - sqrt(16129.0 - 8.0 * (double)m)) * 0.5);
    if (ii < 0) ii = 0;
    if (ii > 62) ii = 62;
    while (ii < 62 && (ii + 1) * (127 - (ii + 1)) / 2 <= m) ii++;
    while (ii > 0 && ii * (127 - ii) / 2 > m) ii--;
    i = ii;
    j = ii + 1 + (m - ii * (127 - ii) / 2);
}

// Fused: blocks [0,256) = proj; blocks [256,320) = scan + edge mask tail.
__global__ void fused_proj_scan(const float* __restrict__ node_feats,
                                const float* __restrict__ eigvec,
                                const float* __restrict__ W_lap,
                                const float* __restrict__ W_edge,
                                const float* __restrict__ b_edge,
                                const float* __restrict__ type_embed,
                                const float* __restrict__ graph_tok,
                                const int*  __restrict__ adj,
                                float* __restrict__ out) {
    __shared__ float sh[256];
    int tid = threadIdx.x;

    if (blockIdx.x < 256) {
        // ---------------- proj ----------------
        int b  = blockIdx.x >> 2;
        int g  = blockIdx.x & 3;
        int n0 = g * 16;
        int d  = tid;

        float wl[LAPD], wu[LAPD], wv[LAPD];
#pragma unroll
        for (int l = 0; l < LAPD; l++) {
            wl[l] = __ldg(&W_lap[l * DD + d]);
            wu[l] = __ldg(&W_edge[(1 + l) * DD + d]);
            wv[l] = __ldg(&W_edge[(1 + LAPD + l) * DD + d]);
        }
        float Cd = __ldg(&W_edge[d]) + __ldg(&b_edge[d]) + __ldg(&type_embed[DD + d]);

        sh[tid] = eigvec[(size_t)(b * NN + n0) * LAPD + tid];
        __syncthreads();

#pragma unroll 4
        for (int n = 0; n < 16; n++) {
            int node = b * NN + n0 + n;
            float nt = node_feats[(size_t)node * DD + d];
            float pu = 0.f, pv = 0.f;
#pragma unroll
            for (int l = 0; l < LAPD; l++) {
                float ev = sh[n * LAPD + l];
                nt += ev * wl[l];
                pu += ev * wu[l];
                pv += ev * wv[l];
            }
            __stcs(&out[((size_t)b * SEQ + 1 + n0 + n) * DD + d], nt);
            g_proju[(size_t)node * DD + d] = pu + Cd;
            g_projv[(size_t)node * DD + d] = pv;
        }

        if (g == 0) {
            __stcs(&out[(size_t)b * SEQ * DD + d], graph_tok[d]);
            float* maskf = out + (size_t)BB * SEQ * DD;
            if (d < 1 + NN) maskf[(size_t)b * SEQ + d] = 0.f;
        }
    } else {
        // ---------------- scan (shuffle-based) + mask tail ----------------
        int b = blockIdx.x - 256;
        const int* adjb = adj + (size_t)b * NN * NN;
        int lane = tid & 31;
        int wid  = tid >> 5;

        int m0 = tid * 8;
        int i, j;
        int v[8], ij[8];
        int local = 0;
        if (m0 < MM) {
            m2ij(m0, i, j);
#pragma unroll
            for (int q = 0; q < 8; q++) {
                int m = m0 + q;
                int val = 0, pack = 0;
                if (m < MM) {
                    pack = (i << 6) | j;
                    val = adjb[i * NN + j] > 0;
                    j++;
                    if (j == NN) { i++; j = i + 1; }
                }
                v[q] = val; ij[q] = pack;
                local += val;
            }
        } else {
#pragma unroll
            for (int q = 0; q < 8; q++) { v[q] = 0; ij[q] = 0; }
        }

        // warp-inclusive scan of local
        int inc = local;
#pragma unroll
        for (int off = 1; off < 32; off <<= 1) {
            int n = __shfl_up_sync(0xFFFFFFFFu, inc, off);
            if (lane >= off) inc += n;
        }
        int* wsum = (int*)sh;
        if (lane == 31) wsum[wid] = inc;
        __syncthreads();
        int woff = 0;
        if (wid > 0) {
#pragma unroll
            for (int w = 0; w < 7; w++)
                if (w < wid) woff += wsum[w];
        }
        int pos = woff + inc - local;   // exclusive prefix
#pragma unroll
        for (int q = 0; q < 8; q++) {
            if (v[q]) g_edge[b * MM + pos++] = (unsigned short)ij[q];
        }
        __syncthreads();
        int total = wsum[0] + wsum[1] + wsum[2] + wsum[3]
                  + wsum[4] + wsum[5] + wsum[6] + wsum[7];
        if (tid == 0) g_count[b] = total;

        float* maskf = out + (size_t)BB * SEQ * DD + (size_t)b * SEQ + 1 + NN;
        for (int k = tid; k < MM; k += 256)
            maskf[k] = (k < total) ? 0.f : 1.f;
    }
}

// Edge kernel, smem-gather version.
// 4 blocks per batch (grid 256), 512 threads, 132KB dynamic smem.
// Each block stages the batch's full proju/projv (64KB+64KB) + edge list (4KB)
// in shared memory, then produces its 504 rows: gathers from SMEM (separate
// pipe), streaming STG.128 to the output. L2 gather traffic 129MB -> ~34MB.
#define EDGE_SMEM_BYTES (64 * 1024 + 64 * 1024 + 4096)
#define ROWS_PER_BLOCK  504

__global__ void __launch_bounds__(512) edge_kernel(float* __restrict__ out) {
    extern __shared__ __align__(16) unsigned char smem_raw[];
    float4* su = (float4*)smem_raw;                  // 4096 float4 = 64KB
    float4* sv = su + NN * (DD / 4);                 // 4096 float4 = 64KB
    unsigned short* sE = (unsigned short*)(sv + NN * (DD / 4));  // 2016 u16

    int b   = blockIdx.x >> 2;
    int q   = blockIdx.x & 3;
    int tid = threadIdx.x;

    const float4* gu = (const float4*)(g_proju + (size_t)b * NN * DD);
    const float4* gv = (const float4*)(g_projv + (size_t)b * NN * DD);
#pragma unroll
    for (int t = 0; t < 8; t++) {
        int idx = tid + t * 512;
        su[idx] = __ldg(&gu[idx]);
        sv[idx] = __ldg(&gv[idx]);
    }
    {
        const unsigned int* ge = (const unsigned int*)(g_edge + b * MM);
        unsigned int* sE32 = (unsigned int*)sE;
        if (tid < 504) {
            sE32[tid] = __ldg(&ge[tid]);
            sE32[tid + 504] = __ldg(&ge[tid + 504]);
        }
    }
    int K = g_count[b];
    __syncthreads();

    int rg   = tid >> 6;        // 0..7
    int lane = tid & 63;
    int base = q * ROWS_PER_BLOCK;

    float4* obase = (float4*)(out + ((size_t)b * SEQ + 1 + NN) * DD);

#pragma unroll 3
    for (int it = 0; it < ROWS_PER_BLOCK / 8; it++) {
        int r = base + it * 8 + rg;
        float4 v = make_float4(0.f, 0.f, 0.f, 0.f);
        if (r < K) {
            int e = sE[r];
            float4 a = su[((e >> 6) << 6) + lane];
            float4 c = sv[((e & 63) << 6) + lane];
            v = make_float4(a.x + c.x, a.y + c.y, a.z + c.z, a.w + c.w);
        }
        __stcs(&obase[(r << 6) + lane], v);
    }
}

extern "C" void kernel_launch(void* const* d_in, const int* in_sizes, int n_in,
                              void* d_out, int out_size) {
    const int*   adj        = (const int*)d_in[0];
    const float* node_feats = (const float*)d_in[1];
    const float* eigvec     = (const float*)d_in[2];
    const float* W_lap      = (const float*)d_in[3];
    const float* W_edge     = (const float*)d_in[4];
    const float* b_edge     = (const float*)d_in[5];
    const float* type_embed = (const float*)d_in[6];
    const float* graph_tok  = (const float*)d_in[7];
    float* out = (float*)d_out;

    static int smem_set = 0;
    if (!smem_set) {
        cudaFuncSetAttribute(edge_kernel,
                             cudaFuncAttributeMaxDynamicSharedMemorySize,
                             EDGE_SMEM_BYTES);
        smem_set = 1;
    }

    fused_proj_scan<<<320, 256>>>(node_feats, eigvec, W_lap, W_edge, b_edge,
                                  type_embed, graph_tok, adj, out);
    edge_kernel<<<256, 512, EDGE_SMEM_BYTES>>>(out);
}